// round 10
// baseline (speedup 1.0000x reference)
#include <cuda_runtime.h>
#include <math.h>

// Problem constants
#define Bv 8
#define Dv 128
#define Mv 1024
#define INVT 14.285714285714286f   // 1/0.07

// GEMM tiling
#define TJ 64
#define TI 64
#define SPLIT 8
#define THREADS 256

// Scratch (device globals; allocation-free)
__device__ __align__(16) float g_f0t[Bv * Dv * Mv];   // [b][k][m], L2-normalized
__device__ __align__(16) float g_f1t[Bv * Dv * Mv];   // [b][k][m], L2-normalized * (1/T)
__device__ __align__(16) float g_diag[Bv * Mv];       // diagonal logits l_jj
__device__ __align__(16) float g_part[SPLIT][Bv * Mv];// partial exp-sums per column
__device__ int g_idx64;                               // 1 if corrs is int64, 0 if int32

// ---------------------------------------------------------------------------
// Kernel 0: detect corrs dtype. Reads first 8192 uint64 words (64 KB), which
// is safe under both dtypes (int32 buffer is exactly 16384*4 = 64 KB).
// If any value >= N when viewed as int64, the data must be packed int32 pairs.
// ---------------------------------------------------------------------------
__global__ void detect_dtype_kernel(const unsigned long long* __restrict__ corrs,
                                    int N) {
    __shared__ int flag;
    if (threadIdx.x == 0) flag = 1;   // assume int64
    __syncthreads();
    for (int i = threadIdx.x; i < 8192; i += 256) {
        if (corrs[i] >= (unsigned long long)N) flag = 0;  // int32 pairs
    }
    __syncthreads();
    if (threadIdx.x == 0) g_idx64 = flag;
}

// ---------------------------------------------------------------------------
// Kernel 1: gather selected rows, L2-normalize, store transposed (k-major).
// One warp per row. 2*B*M = 16384 rows.
// ---------------------------------------------------------------------------
__global__ void gather_norm_kernel(const float* __restrict__ feats0,
                                   const float* __restrict__ feats1,
                                   const void* __restrict__ corrs,
                                   int N) {
    int warp = (blockIdx.x * blockDim.x + threadIdx.x) >> 5;
    int lane = threadIdx.x & 31;
    const int total = 2 * Bv * Mv;
    if (warp >= total) return;

    int half = warp / (Bv * Mv);        // 0 -> feats0/corrs col0, 1 -> feats1/corrs col1
    int rr   = warp % (Bv * Mv);        // b*M + m
    int b    = rr >> 10;
    int m    = rr & (Mv - 1);

    long long idx;
    int ci = rr * 2 + half;
    if (g_idx64) idx = ((const long long*)corrs)[ci];
    else         idx = (long long)((const int*)corrs)[ci];

    const float* __restrict__ src =
        (half == 0 ? feats0 : feats1) + ((long long)b * N + idx) * Dv;

    float4 v = *(const float4*)(src + lane * 4);
    float ss = v.x * v.x + v.y * v.y + v.z * v.z + v.w * v.w;
#pragma unroll
    for (int o = 16; o > 0; o >>= 1) ss += __shfl_xor_sync(0xffffffffu, ss, o);

    float scale = 1.0f / fmaxf(sqrtf(ss), 1e-12f);
    if (half) scale *= INVT;            // fold 1/T into f1

    float* __restrict__ dst = (half == 0 ? g_f0t : g_f1t) + b * (Dv * Mv);
    int k = lane * 4;
    dst[(k + 0) * Mv + m] = v.x * scale;
    dst[(k + 1) * Mv + m] = v.y * scale;
    dst[(k + 2) * Mv + m] = v.z * scale;
    dst[(k + 3) * Mv + m] = v.w * scale;
}

// ---------------------------------------------------------------------------
// Kernel 2: fused logits GEMM + column exp-sum (fixed-shift LSE) + diagonal.
// grid = (M/TJ, SPLIT, B). Block computes a TJ-column stripe over its i-range.
// Shared: sB (f0 tile, full K, k-major) 32KB + sA (f1 tile, half-K) 16KB = 48KB.
// Unit rows => |logit| <= 1/T, so lse = C + log(sum exp(l - C)) with C = 1/T.
// ---------------------------------------------------------------------------
__global__ void __launch_bounds__(THREADS)
logits_lse_kernel() {
    __shared__ __align__(16) float sB[Dv * TJ];   // [k][j]
    __shared__ __align__(16) float sA[64 * TI];   // [k_half][i]; reused as red buf

    const int t  = threadIdx.x;
    const int jt = blockIdx.x;
    const int sp = blockIdx.y;
    const int b  = blockIdx.z;
    const int j0 = jt * TJ;

    const float* __restrict__ F0 = g_f0t + b * (Dv * Mv);
    const float* __restrict__ F1 = g_f1t + b * (Dv * Mv);

    // Load sB: 128 k-rows x 16 float4 (coalesced global, conflict-free STS)
    for (int v = t; v < Dv * (TJ / 4); v += THREADS) {
        int k = v >> 4, jq = v & 15;
        float4 x = *(const float4*)(F0 + k * Mv + j0 + jq * 4);
        *(float4*)(sB + k * TJ + jq * 4) = x;
    }

    const int tx = t & 15;              // j-group
    const int ty = t >> 4;              // i-group
    float esum[4] = {0.f, 0.f, 0.f, 0.f};

    const int iPerSplit = Mv / SPLIT;     // 128
    const int nchunks   = iPerSplit / TI; // 2

    for (int ic = 0; ic < nchunks; ic++) {
        const int ibase = sp * iPerSplit + ic * TI;
        float c[4][4];
#pragma unroll
        for (int ii = 0; ii < 4; ii++)
#pragma unroll
            for (int jj = 0; jj < 4; jj++) c[ii][jj] = 0.f;

#pragma unroll
        for (int kh = 0; kh < 2; kh++) {
            __syncthreads();            // sA safe to overwrite
            for (int v = t; v < 64 * (TI / 4); v += THREADS) {
                int k = v >> 4, iq = v & 15;
                float4 x = *(const float4*)(F1 + (kh * 64 + k) * Mv + ibase + iq * 4);
                *(float4*)(sA + k * TI + iq * 4) = x;
            }
            __syncthreads();

#pragma unroll 8
            for (int k = 0; k < 64; k++) {
                float4 a  = *(const float4*)(sA + k * TI + ty * 4);
                float4 bb = *(const float4*)(sB + (kh * 64 + k) * TJ + tx * 4);
                float av[4] = {a.x, a.y, a.z, a.w};
                float bv[4] = {bb.x, bb.y, bb.z, bb.w};
#pragma unroll
                for (int ii = 0; ii < 4; ii++)
#pragma unroll
                    for (int jj = 0; jj < 4; jj++)
                        c[ii][jj] = fmaf(av[ii], bv[jj], c[ii][jj]);
            }
        }

        // Epilogue: fixed-shift exp accumulate + diagonal capture
#pragma unroll
        for (int ii = 0; ii < 4; ii++) {
            int ig = ibase + ty * 4 + ii;
#pragma unroll
            for (int jj = 0; jj < 4; jj++) {
                int jg = j0 + tx * 4 + jj;
                float l = c[ii][jj];
                esum[jj] += __expf(l - INVT);
                if (ig == jg) g_diag[b * Mv + jg] = l;
            }
        }
    }

    // Reduce esum across ty (16 groups) via reused sA
    __syncthreads();
    float* red = sA;                    // [16][64]
#pragma unroll
    for (int jj = 0; jj < 4; jj++) red[ty * 64 + tx * 4 + jj] = esum[jj];
    __syncthreads();
    if (t < 64) {
        float s = 0.f;
#pragma unroll
        for (int q = 0; q < 16; q++) s += red[q * 64 + t];
        g_part[sp][b * Mv + j0 + t] = s;
    }
}

// ---------------------------------------------------------------------------
// Kernel 3: loss = mean_j ( C + log(sum_j) - diag_j )
// ---------------------------------------------------------------------------
__global__ void finalize_kernel(float* __restrict__ out) {
    __shared__ float red[256];
    int t = threadIdx.x;
    float s = 0.f;
    for (int c = t; c < Bv * Mv; c += 256) {
        float cs = 0.f;
#pragma unroll
        for (int p = 0; p < SPLIT; p++) cs += g_part[p][c];
        s += INVT + logf(cs) - g_diag[c];
    }
    red[t] = s;
    __syncthreads();
    for (int o = 128; o > 0; o >>= 1) {
        if (t < o) red[t] += red[t + o];
        __syncthreads();
    }
    if (t == 0) out[0] = red[0] * (1.0f / (float)(Bv * Mv));
}

// ---------------------------------------------------------------------------
extern "C" void kernel_launch(void* const* d_in, const int* in_sizes, int n_in,
                              void* d_out, int out_size) {
    const float* feats0 = (const float*)d_in[0];
    const float* feats1 = (const float*)d_in[1];
    const void*  corrs  = (const void*)d_in[2];
    int N = in_sizes[0] / (Bv * Dv);    // 20000

    // Kernel 0: corrs dtype detection (int32 vs int64)
    detect_dtype_kernel<<<1, 256>>>((const unsigned long long*)corrs, N);

    // Kernel 1: 16384 warps -> 2048 blocks of 256
    gather_norm_kernel<<<(2 * Bv * Mv) / 8, 256>>>(feats0, feats1, corrs, N);

    // Kernel 2: fused GEMM + exp-sum
    dim3 g2(Mv / TJ, SPLIT, Bv);
    logits_lse_kernel<<<g2, THREADS>>>();

    // Kernel 3: final reduction to scalar
    finalize_kernel<<<1, 256>>>((float*)d_out);
}

// round 11
// speedup vs baseline: 1.1143x; 1.1143x over previous
#include <cuda_runtime.h>
#include <math.h>

// Problem constants
#define Bv 8
#define Dv 128
#define Mv 1024
#define INVT 14.285714285714286f   // 1/0.07

// GEMM tiling
#define TJ 128
#define TI 128
#define KC 32            // k-chunk held in shared
#define SPLIT 8
#define THREADS 256
#define NFIN 32          // finalize stage-1 blocks

typedef unsigned long long u64;

// Scratch (device globals; allocation-free)
__device__ __align__(16) float g_f0t[Bv * Dv * Mv];   // [b][k][m], L2-normalized
__device__ __align__(16) float g_f1t[Bv * Dv * Mv];   // [b][k][m], L2-normalized * (1/T)
__device__ __align__(16) float g_diag[Bv * Mv];       // diagonal logits l_jj
__device__ __align__(16) float g_part[SPLIT][Bv * Mv];// partial exp-sums per column
__device__ float g_bsum[NFIN];                        // finalize stage-1 partials
__device__ int g_idx64;                               // 1 if corrs is int64

// ---------------------------------------------------------------------------
// Packed fp32x2 helpers (Blackwell FFMA2 path, PTX-only)
// ---------------------------------------------------------------------------
__device__ __forceinline__ void fma2(u64& c, u64 a, u64 b) {
    asm("fma.rn.f32x2 %0, %1, %2, %3;" : "=l"(c) : "l"(a), "l"(b), "l"(c));
}
__device__ __forceinline__ u64 dup2(float x) {
    u64 r; unsigned xi = __float_as_uint(x);
    asm("mov.b64 %0, {%1, %1};" : "=l"(r) : "r"(xi));
    return r;
}
__device__ __forceinline__ float2 unpack2(u64 v) {
    unsigned lo, hi;
    asm("mov.b64 {%0, %1}, %2;" : "=r"(lo), "=r"(hi) : "l"(v));
    return make_float2(__uint_as_float(lo), __uint_as_float(hi));
}

// ---------------------------------------------------------------------------
// Kernel 0: detect corrs dtype (int64 vs int32). First 8192 u64 words (64 KB)
// are in-bounds under both dtypes (int32 buffer is exactly 64 KB).
// ---------------------------------------------------------------------------
__global__ void detect_dtype_kernel(const u64* __restrict__ corrs, int N) {
    __shared__ int flag;
    if (threadIdx.x == 0) flag = 1;
    __syncthreads();
    for (int i = threadIdx.x; i < 8192; i += 256)
        if (corrs[i] >= (u64)N) flag = 0;
    __syncthreads();
    if (threadIdx.x == 0) g_idx64 = flag;
}

// ---------------------------------------------------------------------------
// Kernel 1: gather selected rows, L2-normalize, store transposed (k-major).
// One warp per row. 2*B*M = 16384 rows.
// ---------------------------------------------------------------------------
__global__ void gather_norm_kernel(const float* __restrict__ feats0,
                                   const float* __restrict__ feats1,
                                   const void* __restrict__ corrs,
                                   int N) {
    int warp = (blockIdx.x * blockDim.x + threadIdx.x) >> 5;
    int lane = threadIdx.x & 31;
    if (warp >= 2 * Bv * Mv) return;

    int half = warp / (Bv * Mv);
    int rr   = warp % (Bv * Mv);
    int b    = rr >> 10;
    int m    = rr & (Mv - 1);

    long long idx;
    int ci = rr * 2 + half;
    if (g_idx64) idx = ((const long long*)corrs)[ci];
    else         idx = (long long)((const int*)corrs)[ci];

    const float* __restrict__ src =
        (half == 0 ? feats0 : feats1) + ((long long)b * N + idx) * Dv;

    float4 v = *(const float4*)(src + lane * 4);
    float ss = v.x * v.x + v.y * v.y + v.z * v.z + v.w * v.w;
#pragma unroll
    for (int o = 16; o > 0; o >>= 1) ss += __shfl_xor_sync(0xffffffffu, ss, o);

    float scale = 1.0f / fmaxf(sqrtf(ss), 1e-12f);
    if (half) scale *= INVT;

    float* __restrict__ dst = (half == 0 ? g_f0t : g_f1t) + b * (Dv * Mv);
    int k = lane * 4;
    dst[(k + 0) * Mv + m] = v.x * scale;
    dst[(k + 1) * Mv + m] = v.y * scale;
    dst[(k + 2) * Mv + m] = v.z * scale;
    dst[(k + 3) * Mv + m] = v.w * scale;
}

// ---------------------------------------------------------------------------
// Kernel 2: fused 128x128 logits tile GEMM (packed f32x2 FMA) + column
// exp-sum with fixed shift C=1/T + diagonal capture.
// grid = (M/TJ, SPLIT, B), 256 threads, 8x8 microtile as 8x4 f32x2 pairs.
// ---------------------------------------------------------------------------
__global__ void __launch_bounds__(THREADS, 2)
logits_lse_kernel() {
    __shared__ __align__(16) float sA[KC * TI];   // [k][i]  16 KB
    __shared__ __align__(16) float sB[KC * TJ];   // [k][j]  16 KB

    const int t  = threadIdx.x;
    const int j0 = blockIdx.x * TJ;
    const int sp = blockIdx.y;
    const int b  = blockIdx.z;
    const int ibase = sp * (Mv / SPLIT);          // 128-row i stripe

    const float* __restrict__ F0 = g_f0t + b * (Dv * Mv);
    const float* __restrict__ F1 = g_f1t + b * (Dv * Mv);

    const int tx = t & 15;              // j-group: j = j0 + tx*8 + jj
    const int ty = t >> 4;              // i-group: i = ibase + ty*8 + ii

    u64 c2[8][4];
#pragma unroll
    for (int ii = 0; ii < 8; ii++)
#pragma unroll
        for (int jp = 0; jp < 4; jp++) c2[ii][jp] = 0ull;

    for (int kc = 0; kc < Dv / KC; kc++) {
        __syncthreads();                // previous chunk fully consumed
        // load 32 k-rows x 32 float4 per tile; 4 float4 per thread per tile
#pragma unroll
        for (int r = 0; r < 4; r++) {
            int v = t + r * THREADS;    // 0..1023
            int k = v >> 5, q = v & 31;
            const float* pa = F1 + (kc * KC + k) * Mv + ibase + q * 4;
            const float* pb = F0 + (kc * KC + k) * Mv + j0 + q * 4;
            *(float4*)(sA + k * TI + q * 4) = *(const float4*)pa;
            *(float4*)(sB + k * TJ + q * 4) = *(const float4*)pb;
        }
        __syncthreads();

#pragma unroll 4
        for (int k = 0; k < KC; k++) {
            float4 a0 = *(const float4*)(sA + k * TI + ty * 8);
            float4 a1 = *(const float4*)(sA + k * TI + ty * 8 + 4);
            ulonglong2 b0 = *(const ulonglong2*)(sB + k * TJ + tx * 8);
            ulonglong2 b1 = *(const ulonglong2*)(sB + k * TJ + tx * 8 + 4);
            u64 bp[4] = {b0.x, b0.y, b1.x, b1.y};
            float av[8] = {a0.x, a0.y, a0.z, a0.w, a1.x, a1.y, a1.z, a1.w};
#pragma unroll
            for (int ii = 0; ii < 8; ii++) {
                u64 ad = dup2(av[ii]);
#pragma unroll
                for (int jp = 0; jp < 4; jp++) fma2(c2[ii][jp], ad, bp[jp]);
            }
        }
    }

    // Epilogue: exp-accumulate per column + diagonal capture
    float esum[8];
#pragma unroll
    for (int jj = 0; jj < 8; jj++) esum[jj] = 0.f;
#pragma unroll
    for (int ii = 0; ii < 8; ii++) {
        int ig = ibase + ty * 8 + ii;
#pragma unroll
        for (int jp = 0; jp < 4; jp++) {
            float2 l = unpack2(c2[ii][jp]);
            int jg0 = j0 + tx * 8 + jp * 2;
            esum[jp * 2 + 0] += __expf(l.x - INVT);
            esum[jp * 2 + 1] += __expf(l.y - INVT);
            if (ig == jg0)     g_diag[b * Mv + jg0]     = l.x;
            if (ig == jg0 + 1) g_diag[b * Mv + jg0 + 1] = l.y;
        }
    }

    // Cross-ty reduction via reused sA: red[16][128]
    __syncthreads();
    float* red = sA;
#pragma unroll
    for (int jj = 0; jj < 8; jj++) red[ty * TJ + tx * 8 + jj] = esum[jj];
    __syncthreads();
    if (t < TJ) {
        float s = 0.f;
#pragma unroll
        for (int q = 0; q < 16; q++) s += red[q * TJ + t];
        g_part[sp][b * Mv + j0 + t] = s;
    }
}

// ---------------------------------------------------------------------------
// Kernel 3a: per-column loss, 32 blocks x 256 threads (one column/thread).
// ---------------------------------------------------------------------------
__global__ void finalize1_kernel() {
    __shared__ float red[256];
    int t = threadIdx.x;
    int col = blockIdx.x * 256 + t;
    float cs = 0.f;
#pragma unroll
    for (int p = 0; p < SPLIT; p++) cs += g_part[p][col];
    red[t] = INVT + logf(cs) - g_diag[col];
    __syncthreads();
    for (int o = 128; o > 0; o >>= 1) {
        if (t < o) red[t] += red[t + o];
        __syncthreads();
    }
    if (t == 0) g_bsum[blockIdx.x] = red[0];
}

// Kernel 3b: sum 32 partials -> loss
__global__ void finalize2_kernel(float* __restrict__ out) {
    int t = threadIdx.x;
    float s = (t < NFIN) ? g_bsum[t] : 0.f;
#pragma unroll
    for (int o = 16; o > 0; o >>= 1) s += __shfl_xor_sync(0xffffffffu, s, o);
    if (t == 0) out[0] = s * (1.0f / (float)(Bv * Mv));
}

// ---------------------------------------------------------------------------
extern "C" void kernel_launch(void* const* d_in, const int* in_sizes, int n_in,
                              void* d_out, int out_size) {
    const float* feats0 = (const float*)d_in[0];
    const float* feats1 = (const float*)d_in[1];
    const void*  corrs  = (const void*)d_in[2];
    int N = in_sizes[0] / (Bv * Dv);    // 20000

    detect_dtype_kernel<<<1, 256>>>((const u64*)corrs, N);
    gather_norm_kernel<<<(2 * Bv * Mv) / 8, 256>>>(feats0, feats1, corrs, N);

    dim3 g2(Mv / TJ, SPLIT, Bv);        // 8 x 8 x 8 = 512 blocks
    logits_lse_kernel<<<g2, THREADS>>>();

    finalize1_kernel<<<NFIN, 256>>>();
    finalize2_kernel<<<1, 32>>>((float*)d_out);
}